// round 16
// baseline (speedup 1.0000x reference)
#include <cuda_runtime.h>
#include <cstdint>

// CTC batch cost, forward (loss only). B=128, T=1024, C=256 (blank=255),
// Lmax=64, S=129.
//
// BIDIRECTIONAL + WARP-SPECIALIZED:
//   w0: forward alpha consumer  (t = 0..511)
//   w1: backward gamma consumer (t = 1023..512)
//   w2: forward emission producer   w3: backward emission producer
// Producers gather row[cls[s]]+mask into per-state tables padded 8 floats/lane
// (32B) -> consumer reads its 5 probs with LDS.128+LDS.32, conflict-free.
// R16 FIX: backward fast-path loop bounds were i>9 / i>1 (6 iters), dropping
// rows 8 and 0 of every chunk -> rel_err 6.3e-2. Correct mirror of the
// forward path is i>8 / i>0 (7 iters + final step = 8 rows per group).

#define T_DIM   1024
#define C_DIM   256
#define LMAX    64
#define PSTATES 5
#define HALF    512
#define CHUNK   16
#define RAWS    3                         // raw slots per dir
#define TBLS    3                         // table slots per dir
#define HCHUNK  (HALF / CHUNK)            // 32 chunks per half
#define SCANCH  8
#define EPSF    1e-7f
#define MFLOOR  1e-37f
#define NEGL    -1e30f
#define SLOT_WORDS 4096                   // 16 rows * 256 words = 16KB
#define RAW_BYTES  (2 * RAWS * SLOT_WORDS * 4)   // 96KB
#define TBL_BYTES  (2 * TBLS * SLOT_WORDS * 4)   // 96KB
#define DSMEM_BYTES (RAW_BYTES + TBL_BYTES)      // 192KB

__global__ __launch_bounds__(128, 1)
void ctc_loss_kernel(const int*   __restrict__ y_true,   // [B, LMAX]
                     const float* __restrict__ y_pred,   // [B, T, C]
                     const int*   __restrict__ in_len,   // [B, 1]
                     const int*   __restrict__ lab_len,  // [B, 1]
                     float*       __restrict__ out)      // [B, 1]
{
    extern __shared__ __align__(128) float stage[];
    __shared__ __align__(8) uint64_t mbar[18];  // raw[6], tblF[6], tblE[6]
    __shared__ float fa [32 * PSTATES];
    __shared__ float fg [32 * PSTATES];
    __shared__ float flc[32], glc[32];

    const int b    = blockIdx.x;
    const int tid  = threadIdx.x;
    const int wid  = tid >> 5;
    const int lane = tid & 31;
    const int dir  = wid & 1;              // 0 = fwd, 1 = bwd
    const char* __restrict__ gbase =
        (const char*)(y_pred + (size_t)b * T_DIM * C_DIM);
    const int L    = lab_len[b];
    const int Tlen = in_len[b];
    const int Smax = 2 * L + 1;
    const int* __restrict__ yb = y_true + b * LMAX;

    uint32_t stage_addr, mbar_addr;
    asm("{ .reg .u64 t; cvta.to.shared.u64 t, %1; cvt.u32.u64 %0, t; }"
        : "=r"(stage_addr) : "l"((const void*)stage));
    asm("{ .reg .u64 t; cvta.to.shared.u64 t, %1; cvt.u32.u64 %0, t; }"
        : "=r"(mbar_addr) : "l"((const void*)mbar));

    if (tid == 0) {
        #pragma unroll
        for (int s = 0; s < 18; s++)
            asm volatile("mbarrier.init.shared.b64 [%0], 1;"
                         :: "r"(mbar_addr + s * 8) : "memory");
        asm volatile("fence.proxy.async.shared::cta;" ::: "memory");
    }
    __syncthreads();

    // ---- shared helpers ----
    auto mb_wait = [&](int idx, uint32_t parity) {
        uint32_t mb = mbar_addr + (uint32_t)idx * 8;
        asm volatile(
            "{\n\t.reg .pred P;\n\t"
            "W_%=:\n\t"
            "mbarrier.try_wait.parity.acquire.cta.shared::cta.b64 P, [%0], %1, 0x989680;\n\t"
            "@!P bra W_%=;\n\t}"
            :: "r"(mb), "r"(parity) : "memory");
    };
    auto mb_arrive = [&](int idx) {
        asm volatile("mbarrier.arrive.shared::cta.b64 _, [%0];"
                     :: "r"(mbar_addr + (uint32_t)idx * 8) : "memory");
    };
    auto raw_slot = [&](int k) -> float* {
        return stage + (size_t)(dir * RAWS + (k % RAWS)) * SLOT_WORDS;
    };
    auto tbl_slot = [&](int k) -> float* {
        return stage + (size_t)(2 * RAWS + dir * TBLS + (k % TBLS)) * SLOT_WORDS;
    };
    const int RAWB = dir * RAWS;          // raw mbar base
    const int TFB  = 6 + dir * TBLS;      // table-full mbar base
    const int TEB  = 12 + dir * TBLS;     // table-empty mbar base

    if (wid >= 2) {
        // ========================= PRODUCERS =========================
        int   cls[PSTATES];
        float vm [PSTATES], evm[PSTATES];
        #pragma unroll
        for (int j = 0; j < PSTATES; j++) {
            int s   = lane * PSTATES + j;
            int li  = (s - 1) >> 1;
            int c   = ((s & 1) && li >= 0 && li < LMAX) ? yb[li] : (C_DIM - 1);
            bool valid = (s < Smax);
            cls[j] = c;
            vm [j] = valid ? 1.0f : 0.0f;
            evm[j] = valid ? EPSF : 0.0f;
        }
        auto issue_raw = [&](int k) {
            if (lane == 0 && k < HCHUNK) {
                int gchunk = dir ? (63 - k) : k;
                uint32_t slot = (uint32_t)(dir * RAWS + (k % RAWS));
                uint32_t mb   = mbar_addr + (RAWB + (k % RAWS)) * 8;
                uint32_t dst  = stage_addr + slot * (SLOT_WORDS * 4);
                const char* src = gbase + (size_t)gchunk * (SLOT_WORDS * 4);
                asm volatile(
                    "mbarrier.arrive.expect_tx.shared::cta.b64 _, [%0], %1;"
                    :: "r"(mb), "n"(SLOT_WORDS * 4) : "memory");
                asm volatile(
                    "cp.async.bulk.shared::cluster.global.mbarrier::complete_tx::bytes"
                    " [%0], [%1], %2, [%3];"
                    :: "r"(dst), "l"(src), "n"(SLOT_WORDS * 4), "r"(mb) : "memory");
            }
        };
        for (int k = 0; k < RAWS; k++) issue_raw(k);

        for (int k = 0; k < HCHUNK; k++) {
            uint32_t u = (uint32_t)(k / 3);
            mb_wait(RAWB + (k % RAWS), u & 1u);          // raw data resident
            mb_wait(TEB  + (k % TBLS), (u & 1u) ^ 1u);   // consumer freed slot
            const float* __restrict__ raw = raw_slot(k);
            float* __restrict__ tb = tbl_slot(k);
            #pragma unroll 4
            for (int r = 0; r < CHUNK; r++) {
                const float* __restrict__ row = raw + r * C_DIM;
                float p0 = fmaf(row[cls[0]], vm[0], evm[0]);
                float p1 = fmaf(row[cls[1]], vm[1], evm[1]);
                float p2 = fmaf(row[cls[2]], vm[2], evm[2]);
                float p3 = fmaf(row[cls[3]], vm[3], evm[3]);
                float p4 = fmaf(row[cls[4]], vm[4], evm[4]);
                float* dst = tb + r * C_DIM + lane * 8;
                *reinterpret_cast<float4*>(dst) = make_float4(p0, p1, p2, p3);
                dst[4] = p4;
            }
            __syncwarp();
            if (lane == 0) mb_arrive(TFB + (k % TBLS));  // table full
            issue_raw(k + RAWS);                         // refill raw slot
        }
    } else if (wid == 0) {
        // ================= FORWARD CONSUMER: alpha, t = 0..511 =============
        float m2[PSTATES];
        #pragma unroll
        for (int j = 0; j < PSTATES; j++) {
            int s  = lane * PSTATES + j;
            int li = (s - 1) >> 1;
            bool skip = (s & 1) && (s >= 3) && (li < LMAX) && (yb[li] != yb[li - 1]);
            m2[j] = skip ? 1.0f : 0.0f;
        }
        float a[PSTATES];
        int   ilog = 0;
        float rho  = (lane == 0) ? 0.0f : 1.0f;

        float4 q; float q4;
        auto ld = [&](const float* tb, int r, float4& oq, float& oq4) {
            const float* p = tb + r * C_DIM + lane * 8;
            oq  = *reinterpret_cast<const float4*>(p);
            oq4 = p[4];
        };
        auto stepq = [&](const float4& p, float p4) {
            float h1 = __shfl_up_sync(0xffffffffu, a[4], 1) * rho;
            float h2 = __shfl_up_sync(0xffffffffu, a[3], 1) * rho;
            float n0 = fmaf(h2,   m2[0], a[0] + h1)   * p.x;
            float n1 = fmaf(h1,   m2[1], a[1] + a[0]) * p.y;
            float n2 = fmaf(a[0], m2[2], a[2] + a[1]) * p.z;
            float n3 = fmaf(a[1], m2[3], a[3] + a[2]) * p.w;
            float n4 = fmaf(a[2], m2[4], a[4] + a[3]) * p4;
            a[0] = n0; a[1] = n1; a[2] = n2; a[3] = n3; a[4] = n4;
        };
        auto stepg = [&](int t, const float* tb, int r) {
            if (t < Tlen) { float4 tq; float tq4; ld(tb, r, tq, tq4); stepq(tq, tq4); }
        };
        auto apply_scale = [&](float v) {
            int ebits = __float_as_int(v) >> 23;
            int eprev = __shfl_up_sync(0xffffffffu, ebits, 1);
            ilog += ebits - 127;
            float rinv = __int_as_float((254 - ebits) << 23);
            int d = eprev - ebits;
            d = (d > 60) ? 60 : ((d < -126) ? -126 : d);
            rho = fminf(rho * __int_as_float((d + 127) << 23), 1e30f);
            #pragma unroll
            for (int j = 0; j < PSTATES; j++) a[j] *= rinv;
        };
        auto renorm_scan = [&]() {
            float v = fmaxf(fmaxf(fmaxf(a[0], a[1]), fmaxf(a[2], a[3])), a[4]);
            #pragma unroll
            for (int d = 1; d < 32; d <<= 1) {
                float up = __shfl_up_sync(0xffffffffu, v, d);
                v = (v > 0.0f) ? v : up;
            }
            apply_scale(fmaxf(v, MFLOOR));
        };
        auto renorm_fast = [&]() {
            float v = fmaxf(fmaxf(fmaxf(a[0], a[1]), fmaxf(a[2], a[3])), a[4]);
            apply_scale(fmaxf(v, MFLOOR));
        };

        for (int k = 0; k < HCHUNK; k++) {
            uint32_t u = (uint32_t)(k / 3);
            mb_wait(TFB + (k % TBLS), u & 1u);           // table ready
            const float* __restrict__ tb = tbl_slot(k);
            const int t0 = k * CHUNK;
            const bool scan = (k < SCANCH);
            if (k == 0) {
                ld(tb, 0, q, q4);
                float pv[PSTATES] = {q.x, q.y, q.z, q.w, q4};
                #pragma unroll
                for (int j = 0; j < PSTATES; j++) {
                    int s = lane * PSTATES + j;
                    a[j]  = (s < 2) ? pv[j] : 0.0f;
                }
                #pragma unroll
                for (int i = 1; i < 8; i++) stepg(i, tb, i);
                renorm_scan();
                #pragma unroll
                for (int i = 8; i < CHUNK; i++) stepg(i, tb, i);
                __syncwarp();
                if (lane == 0) mb_arrive(TEB + (k % TBLS));
                renorm_scan();
            } else if (t0 + CHUNK <= Tlen) {             // fast path
                ld(tb, 0, q, q4);
                #pragma unroll
                for (int i = 0; i < 7; i++) {            // steps rows 0..6
                    float4 nq; float nq4; ld(tb, i + 1, nq, nq4);
                    stepq(q, q4); q = nq; q4 = nq4;
                }
                stepq(q, q4);                            // row 7
                ld(tb, 8, q, q4);                        // covered by renorm
                if (scan) renorm_scan(); else renorm_fast();
                #pragma unroll
                for (int i = 8; i < 15; i++) {           // steps rows 8..14
                    float4 nq; float nq4; ld(tb, i + 1, nq, nq4);
                    stepq(q, q4); q = nq; q4 = nq4;
                }
                stepq(q, q4);                            // row 15
                __syncwarp();
                if (lane == 0) mb_arrive(TEB + (k % TBLS));
                if (scan) renorm_scan(); else renorm_fast();
            } else {                                     // boundary chunk
                #pragma unroll
                for (int i = 0; i < 8; i++) stepg(t0 + i, tb, i);
                if (scan) renorm_scan(); else renorm_fast();
                #pragma unroll
                for (int i = 8; i < CHUNK; i++) stepg(t0 + i, tb, i);
                __syncwarp();
                if (lane == 0) mb_arrive(TEB + (k % TBLS));
                if (scan) renorm_scan(); else renorm_fast();
            }
        }
        #pragma unroll
        for (int j = 0; j < PSTATES; j++) fa[lane * PSTATES + j] = a[j];
        flc[lane] = (float)ilog * 0.6931471805599453f;
    } else {
        // ================ BACKWARD CONSUMER: gamma, t = 1023..512 ==========
        float m2b[PSTATES];
        #pragma unroll
        for (int j = 0; j < PSTATES; j++) {
            int s  = lane * PSTATES + j;
            int li = (s - 1) >> 1;
            bool skip = (s & 1) && (li + 1 < LMAX) && (yb[li + 1] != yb[li]);
            m2b[j] = skip ? 1.0f : 0.0f;
        }
        float g[PSTATES];
        int   ilog  = 0;
        float rho_b = (lane == 31) ? 0.0f : 1.0f;
        bool  virgin = true;
        #pragma unroll
        for (int j = 0; j < PSTATES; j++) {
            int s = lane * PSTATES + j;
            g[j] = (s == 2 * L || s == 2 * L - 1) ? 1.0f : 0.0f;
        }

        float4 q; float q4;
        auto ld = [&](const float* tb, int r, float4& oq, float& oq4) {
            const float* p = tb + r * C_DIM + lane * 8;
            oq  = *reinterpret_cast<const float4*>(p);
            oq4 = p[4];
        };
        auto stepq = [&](const float4& p, float p4) {
            float h5 = __shfl_down_sync(0xffffffffu, g[0], 1) * rho_b;
            float h6 = __shfl_down_sync(0xffffffffu, g[1], 1) * rho_b;
            float n0 = fmaf(m2b[0], g[2], g[0] + g[1]) * p.x;
            float n1 = fmaf(m2b[1], g[3], g[1] + g[2]) * p.y;
            float n2 = fmaf(m2b[2], g[4], g[2] + g[3]) * p.z;
            float n3 = fmaf(m2b[3], h5,   g[3] + g[4]) * p.w;
            float n4 = fmaf(m2b[4], h6,   g[4] + h5  ) * p4;
            g[0] = n0; g[1] = n1; g[2] = n2; g[3] = n3; g[4] = n4;
        };
        auto stepg_ = [&](int t, const float* tb, int r) {
            if (t < Tlen) {
                float4 tq; float tq4; ld(tb, r, tq, tq4);
                if (virgin) {
                    float pv[PSTATES] = {tq.x, tq.y, tq.z, tq.w, tq4};
                    #pragma unroll
                    for (int j = 0; j < PSTATES; j++) g[j] *= pv[j];
                    virgin = false;
                } else stepq(tq, tq4);
            }
        };
        auto apply_scale_b = [&](float v) {
            int ebits = __float_as_int(v) >> 23;
            int enext = __shfl_down_sync(0xffffffffu, ebits, 1);
            ilog += ebits - 127;
            float rinv = __int_as_float((254 - ebits) << 23);
            int d = enext - ebits;
            d = (d > 60) ? 60 : ((d < -126) ? -126 : d);
            rho_b = fminf(rho_b * __int_as_float((d + 127) << 23), 1e30f);
            #pragma unroll
            for (int j = 0; j < PSTATES; j++) g[j] *= rinv;
        };
        auto renorm_scan_b = [&]() {
            float v = fmaxf(fmaxf(fmaxf(g[0], g[1]), fmaxf(g[2], g[3])), g[4]);
            #pragma unroll
            for (int d = 1; d < 32; d <<= 1) {
                float dn = __shfl_down_sync(0xffffffffu, v, d);
                v = (v > 0.0f) ? v : dn;
            }
            apply_scale_b(fmaxf(v, MFLOOR));
        };
        auto renorm_fast_b = [&]() {
            float v = fmaxf(fmaxf(fmaxf(g[0], g[1]), fmaxf(g[2], g[3])), g[4]);
            apply_scale_b(fmaxf(v, MFLOOR));
        };

        for (int k = 0; k < HCHUNK; k++) {
            uint32_t u = (uint32_t)(k / 3);
            mb_wait(TFB + (k % TBLS), u & 1u);
            const float* __restrict__ tb = tbl_slot(k);
            const int tbase = (63 - k) * CHUNK;
            const bool scan = (k < SCANCH);
            if (!virgin && (tbase + CHUNK <= Tlen)) {    // fast path
                ld(tb, 15, q, q4);
                #pragma unroll
                for (int i = 15; i > 8; i--) {           // steps rows 15..9 (FIX)
                    float4 nq; float nq4; ld(tb, i - 1, nq, nq4);
                    stepq(q, q4); q = nq; q4 = nq4;
                }
                stepq(q, q4);                            // row 8 (FIX)
                ld(tb, 7, q, q4);
                if (scan) renorm_scan_b(); else renorm_fast_b();
                #pragma unroll
                for (int i = 7; i > 0; i--) {            // steps rows 7..1 (FIX)
                    float4 nq; float nq4; ld(tb, i - 1, nq, nq4);
                    stepq(q, q4); q = nq; q4 = nq4;
                }
                stepq(q, q4);                            // row 0 (FIX)
                __syncwarp();
                if (lane == 0) mb_arrive(TEB + (k % TBLS));
                if (scan) renorm_scan_b(); else renorm_fast_b();
            } else {                                     // guarded (k==0/tail)
                #pragma unroll
                for (int i = CHUNK - 1; i >= 8; i--) stepg_(tbase + i, tb, i);
                if (scan) renorm_scan_b(); else renorm_fast_b();
                #pragma unroll
                for (int i = 7; i >= 0; i--) stepg_(tbase + i, tb, i);
                __syncwarp();
                if (lane == 0) mb_arrive(TEB + (k % TBLS));
                if (scan) renorm_scan_b(); else renorm_fast_b();
            }
        }
        #pragma unroll
        for (int j = 0; j < PSTATES; j++) fg[lane * PSTATES + j] = g[j];
        glc[lane] = (float)ilog * 0.6931471805599453f;
    }

    __syncthreads();

    // ===================== COMBINE (warp 0, log space) =====================
    if (wid == 0) {
        if (Tlen > HALF) {
            float vals[PSTATES];
            float M = NEGL;
            #pragma unroll
            for (int j = 0; j < PSTATES; j++) {
                int s = lane * PSTATES + j;
                float v = NEGL;
                if (s < Smax) {
                    float la = __logf(fmaxf(fa[s], MFLOOR)) + flc[lane];
                    float t0 = __logf(fmaxf(fg[s], MFLOOR)) + glc[lane];
                    float t1 = NEGL, t2 = NEGL;
                    if (s + 1 < Smax)
                        t1 = __logf(fmaxf(fg[s + 1], MFLOOR)) + glc[(s + 1) / PSTATES];
                    if ((s & 1) && (s + 2 < Smax)) {
                        int li = (s - 1) >> 1;
                        if (li + 1 < LMAX && yb[li + 1] != yb[li])
                            t2 = __logf(fmaxf(fg[s + 2], MFLOOR)) + glc[(s + 2) / PSTATES];
                    }
                    float m3 = fmaxf(t0, fmaxf(t1, t2));
                    float lmix = m3 + __logf(__expf(t0 - m3) + __expf(t1 - m3) +
                                             __expf(t2 - m3));
                    v = la + lmix;
                }
                vals[j] = v;
                M = fmaxf(M, v);
            }
            #pragma unroll
            for (int o = 16; o > 0; o >>= 1)
                M = fmaxf(M, __shfl_xor_sync(0xffffffffu, M, o));
            float ssum = 0.0f;
            #pragma unroll
            for (int j = 0; j < PSTATES; j++) ssum += __expf(vals[j] - M);
            #pragma unroll
            for (int o = 16; o > 0; o >>= 1)
                ssum += __shfl_xor_sync(0xffffffffu, ssum, o);
            if (lane == 0) out[b] = -(M + __logf(ssum));
        } else if (lane == 0) {
            int  sa = 2 * L, sb = 2 * L - 1;
            float xa = __logf(fmaxf(fa[sa], MFLOOR)) + flc[sa / PSTATES];
            float xb = __logf(fmaxf(fa[sb], MFLOOR)) + flc[sb / PSTATES];
            float mxx = fmaxf(xa, xb), mnn = fminf(xa, xb);
            out[b] = -(mxx + __logf(1.0f + __expf(mnn - mxx)));
        }
    }
}

extern "C" void kernel_launch(void* const* d_in, const int* in_sizes, int n_in,
                              void* d_out, int out_size) {
    const int*   y_true  = (const int*)  d_in[0];   // [B,64] int32
    const float* y_pred  = (const float*)d_in[1];   // [B,1024,256] fp32
    const int*   in_len  = (const int*)  d_in[2];   // [B,1] int32
    const int*   lab_len = (const int*)  d_in[3];   // [B,1] int32
    float*       out     = (float*)      d_out;     // [B,1] fp32

    cudaFuncSetAttribute(ctc_loss_kernel,
                         cudaFuncAttributeMaxDynamicSharedMemorySize,
                         DSMEM_BYTES);

    const int B = out_size;                          // 128
    ctc_loss_kernel<<<B, 128, DSMEM_BYTES>>>(y_true, y_pred, in_len, lab_len, out);
}

// round 17
// speedup vs baseline: 1.4531x; 1.4531x over previous
#include <cuda_runtime.h>
#include <cstdint>

// CTC batch cost, forward (loss only). B=128, T=1024, C=256 (blank=255),
// Lmax=64, S=129.
//
// BIDIRECTIONAL (R14 base, 33.1us) + PARITY-ALIGNED 4-STATE LAYOUT (this rd):
//   s = 4*lane + j  => j=0,2 always blank states, j=1,3 always label states.
//   - 3 LDS/step (1 broadcast blank + 2 label gathers) instead of 5
//   - forward needs ONE shfl/step (even states never skip)
//   - state 128 rides as scalar e on lane 31 (masked, branchless)
// Consumers are ~73% issue-bound (R14 ncu, per-SMSP) => fewer issued
// instructions/step is the lever. Warp-specialized producers REVERTED (R16
// regression). 2 warps: w0 fwd alpha t=0..511, w1 bwd gamma t=1023..512.

#define T_DIM   1024
#define C_DIM   256
#define LMAX    64
#define NST     4                         // states per lane (+ e on lane31)
#define HALF    512
#define CHUNK   16
#define RINGC   4                         // ring slots per warp
#define HCHUNK  (HALF / CHUNK)            // 32
#define SCANCH  8
#define EPSF    1e-7f
#define MFLOOR  1e-37f
#define NEGL    -1e30f
#define CHUNK_BYTES (CHUNK * C_DIM * 4)   // 16384
#define RING_BYTES  (2 * RINGC * CHUNK_BYTES) // 131072

__global__ __launch_bounds__(64, 1)
void ctc_loss_kernel(const int*   __restrict__ y_true,   // [B, LMAX]
                     const float* __restrict__ y_pred,   // [B, T, C]
                     const int*   __restrict__ in_len,   // [B, 1]
                     const int*   __restrict__ lab_len,  // [B, 1]
                     float*       __restrict__ out)      // [B, 1]
{
    extern __shared__ __align__(128) float stage[];      // 2 rings x 64KB
    __shared__ __align__(8) uint64_t mbar[2 * RINGC];
    __shared__ float fa [132];            // alpha_511 by state (0..128)
    __shared__ float fg [132];            // gamma_512 by state (0..128)
    __shared__ float flc[32], glc[32];

    const int b    = blockIdx.x;
    const int tid  = threadIdx.x;
    const int wid  = tid >> 5;
    const int lane = tid & 31;
    const char* __restrict__ gbase =
        (const char*)(y_pred + (size_t)b * T_DIM * C_DIM);
    const int L    = lab_len[b];
    const int Tlen = in_len[b];
    const int Smax = 2 * L + 1;
    const int* __restrict__ yb = y_true + b * LMAX;

    uint32_t stage_addr, mbar_addr;
    asm("{ .reg .u64 t; cvta.to.shared.u64 t, %1; cvt.u32.u64 %0, t; }"
        : "=r"(stage_addr) : "l"((const void*)stage));
    asm("{ .reg .u64 t; cvta.to.shared.u64 t, %1; cvt.u32.u64 %0, t; }"
        : "=r"(mbar_addr) : "l"((const void*)mbar));

    // ---- per-lane constants (parity-aligned: j=0,2 blank; j=1,3 labels) ----
    const int s0 = 4 * lane;
    const int li1 = 2 * lane;             // label idx for j=1 (s=4l+1)
    const int li3 = 2 * lane + 1;         // label idx for j=3 (s=4l+3)
    const int cls1 = yb[li1];             // li1 <= 62 < LMAX always
    const int cls3 = yb[li3];             // li3 <= 63 < LMAX always
    float vm0 = (s0     < Smax) ? 1.0f : 0.0f;
    float vm1 = (s0 + 1 < Smax) ? 1.0f : 0.0f;
    float vm2 = (s0 + 2 < Smax) ? 1.0f : 0.0f;
    float vm3 = (s0 + 3 < Smax) ? 1.0f : 0.0f;
    float vme = (lane == 31 && 128 < Smax) ? 1.0f : 0.0f;   // state 128 (L==64)
    float ev0 = vm0 * EPSF, ev1 = vm1 * EPSF, ev2 = vm2 * EPSF,
          ev3 = vm3 * EPSF, eve = vme * EPSF;

    if (tid == 0) {
        #pragma unroll
        for (int s = 0; s < 2 * RINGC; s++)
            asm volatile("mbarrier.init.shared.b64 [%0], 1;"
                         :: "r"(mbar_addr + s * 8) : "memory");
        asm volatile("fence.proxy.async.shared::cta;" ::: "memory");
    }
    __syncthreads();

    const int warpbase = wid * RINGC;
    auto issue_k = [&](int k) {
        if (lane == 0 && k < HCHUNK) {
            int gchunk = (wid == 0) ? k : (63 - k);
            uint32_t slot = (uint32_t)(warpbase + (k & (RINGC - 1)));
            uint32_t mb   = mbar_addr + slot * 8;
            uint32_t dst  = stage_addr + slot * CHUNK_BYTES;
            const char* src = gbase + (size_t)gchunk * CHUNK_BYTES;
            asm volatile(
                "mbarrier.arrive.expect_tx.shared::cta.b64 _, [%0], %1;"
                :: "r"(mb), "n"(CHUNK_BYTES) : "memory");
            asm volatile(
                "cp.async.bulk.shared::cluster.global.mbarrier::complete_tx::bytes"
                " [%0], [%1], %2, [%3];"
                :: "r"(dst), "l"(src), "n"(CHUNK_BYTES), "r"(mb) : "memory");
        }
    };
    auto wait_k = [&](int k) {
        uint32_t mb = mbar_addr + (uint32_t)(warpbase + (k & (RINGC - 1))) * 8;
        uint32_t parity = ((uint32_t)k >> 2) & 1u;
        asm volatile(
            "{\n\t.reg .pred P;\n\t"
            "W_%=:\n\t"
            "mbarrier.try_wait.parity.acquire.cta.shared::cta.b64 P, [%0], %1, 0x989680;\n\t"
            "@!P bra W_%=;\n\t}"
            :: "r"(mb), "r"(parity) : "memory");
    };
    auto slot_rows = [&](int k) -> const float* {
        return stage + (size_t)(warpbase + (k & (RINGC - 1))) * (CHUNK_BYTES / 4);
    };

    if (wid == 0) {
        // ================= FORWARD: alpha + e, t = 0..511 =================
        // skip masks: only odd states skip. j=1: s=4l+1, li=2l, prev=2l-1
        float m21 = (lane >= 1 && yb[li1] != yb[li1 - 1]) ? 1.0f : 0.0f;
        float m23 = (cls3 != cls1) ? 1.0f : 0.0f;      // li=2l+1 vs 2l
        float a0, a1, a2, a3, e = 0.0f;
        int   ilog = 0;
        float rho  = (lane == 0) ? 0.0f : 1.0f;

        auto step1u = [&](const float* __restrict__ row) {
            float h1 = __shfl_up_sync(0xffffffffu, a3, 1) * rho;
            float pb = row[255];
            float l1 = row[cls1];
            float l3 = row[cls3];
            float p0 = fmaf(pb, vm0, ev0);
            float p1 = fmaf(l1, vm1, ev1);
            float p2 = fmaf(pb, vm2, ev2);
            float p3 = fmaf(l3, vm3, ev3);
            float pe = fmaf(pb, vme, eve);
            float n0 = (a0 + h1) * p0;                  // even: no skip
            float n1 = fmaf(h1, m21, a1 + a0) * p1;
            float n2 = (a2 + a1) * p2;                  // even: no skip
            float n3 = fmaf(a1, m23, a3 + a2) * p3;
            e  = (e + a3) * pe;                         // state 128 (lane31)
            a0 = n0; a1 = n1; a2 = n2; a3 = n3;
        };
        auto step1g = [&](int t, const float* __restrict__ row) {
            if (t < Tlen) step1u(row);
        };
        auto apply_scale = [&](float v) {
            int ebits = __float_as_int(v) >> 23;
            int eprev = __shfl_up_sync(0xffffffffu, ebits, 1);
            ilog += ebits - 127;
            float rinv = __int_as_float((254 - ebits) << 23);
            int d = eprev - ebits;
            d = (d > 60) ? 60 : ((d < -126) ? -126 : d);
            rho = fminf(rho * __int_as_float((d + 127) << 23), 1e30f);
            a0 *= rinv; a1 *= rinv; a2 *= rinv; a3 *= rinv; e *= rinv;
        };
        auto renorm_scan = [&]() {
            float v = fmaxf(fmaxf(a0, a1), fmaxf(fmaxf(a2, a3), e));
            #pragma unroll
            for (int d = 1; d < 32; d <<= 1) {
                float up = __shfl_up_sync(0xffffffffu, v, d);
                v = (v > 0.0f) ? v : up;
            }
            apply_scale(fmaxf(v, MFLOOR));
        };
        auto renorm_fast = [&]() {
            float v = fmaxf(fmaxf(a0, a1), fmaxf(fmaxf(a2, a3), e));
            apply_scale(fmaxf(v, MFLOOR));
        };

        for (int k = 0; k < RINGC - 1; k++) issue_k(k);

        wait_k(0);
        __syncwarp();
        issue_k(RINGC - 1);
        {
            const float* __restrict__ rows = slot_rows(0);
            float pb = rows[255], l1v = rows[cls1];
            a0 = (s0 == 0) ? fmaf(pb, vm0, ev0) : 0.0f;        // s=0
            a1 = (s0 + 1 == 1) ? fmaf(l1v, vm1, ev1) : 0.0f;   // s=1
            a2 = 0.0f; a3 = 0.0f;
            #pragma unroll
            for (int i = 1; i < 8; i++) step1g(i, rows + i * C_DIM);
            renorm_scan();
            #pragma unroll
            for (int i = 8; i < CHUNK; i++) step1g(i, rows + i * C_DIM);
            renorm_scan();
        }
        for (int k = 1; k < HCHUNK; k++) {
            wait_k(k);
            __syncwarp();
            issue_k(k + RINGC - 1);
            const float* __restrict__ rows = slot_rows(k);
            const int t0 = k * CHUNK;
            const bool scan = (k < SCANCH);
            if (t0 + CHUNK <= Tlen) {
                #pragma unroll
                for (int i = 0; i < 8; i++) step1u(rows + i * C_DIM);
                if (scan) renorm_scan(); else renorm_fast();
                #pragma unroll
                for (int i = 8; i < CHUNK; i++) step1u(rows + i * C_DIM);
                if (scan) renorm_scan(); else renorm_fast();
            } else {
                #pragma unroll
                for (int i = 0; i < 8; i++) step1g(t0 + i, rows + i * C_DIM);
                if (scan) renorm_scan(); else renorm_fast();
                #pragma unroll
                for (int i = 8; i < CHUNK; i++) step1g(t0 + i, rows + i * C_DIM);
                if (scan) renorm_scan(); else renorm_fast();
            }
        }
        fa[s0] = a0; fa[s0 + 1] = a1; fa[s0 + 2] = a2; fa[s0 + 3] = a3;
        if (lane == 31) fa[128] = e;
        flc[lane] = (float)ilog * 0.6931471805599453f;
    } else {
        // ================ BACKWARD: gamma + e, t = 1023..512 ==============
        // skip (source-based, odd s): j=1: li=2l vs 2l+1; j=3: li=2l+1 vs 2l+2
        float m2b1 = (cls1 != cls3) ? 1.0f : 0.0f;
        float m2b3 = (li3 + 1 < LMAX && yb[li3 + 1] != cls3) ? 1.0f : 0.0f;
        float g0, g1, g2, g3, e;
        int   ilog  = 0;
        float rho_b = (lane == 31) ? 0.0f : 1.0f;
        bool  virgin = true;
        g0 = (s0     == 2 * L || s0     == 2 * L - 1) ? 1.0f : 0.0f;
        g1 = (s0 + 1 == 2 * L || s0 + 1 == 2 * L - 1) ? 1.0f : 0.0f;
        g2 = (s0 + 2 == 2 * L || s0 + 2 == 2 * L - 1) ? 1.0f : 0.0f;
        g3 = (s0 + 3 == 2 * L || s0 + 3 == 2 * L - 1) ? 1.0f : 0.0f;
        e  = (lane == 31 && 2 * L == 128) ? 1.0f : 0.0f;

        auto stepbu = [&](const float* __restrict__ row) {
            float h0 = fmaf(__shfl_down_sync(0xffffffffu, g0, 1), rho_b, e);
            float h1 = __shfl_down_sync(0xffffffffu, g1, 1) * rho_b;
            float pb = row[255];
            float l1 = row[cls1];
            float l3 = row[cls3];
            float p0 = fmaf(pb, vm0, ev0);
            float p1 = fmaf(l1, vm1, ev1);
            float p2 = fmaf(pb, vm2, ev2);
            float p3 = fmaf(l3, vm3, ev3);
            float pe = fmaf(pb, vme, eve);
            float n0 = (g0 + g1) * p0;                  // even: no skip
            float n1 = fmaf(m2b1, g3, g1 + g2) * p1;
            float n2 = (g2 + g3) * p2;                  // even: no skip
            float n3 = fmaf(m2b3, h1, g3 + h0) * p3;
            e  = e * pe;                                // state 128: only self
            g0 = n0; g1 = n1; g2 = n2; g3 = n3;
        };
        auto stepbg = [&](int t, const float* __restrict__ row) {
            if (t < Tlen) {
                if (virgin) {
                    float pb = row[255], l1 = row[cls1], l3 = row[cls3];
                    g0 *= fmaf(pb, vm0, ev0);
                    g1 *= fmaf(l1, vm1, ev1);
                    g2 *= fmaf(pb, vm2, ev2);
                    g3 *= fmaf(l3, vm3, ev3);
                    e  *= fmaf(pb, vme, eve);
                    virgin = false;
                } else stepbu(row);
            }
        };
        auto apply_scale_b = [&](float v) {
            int ebits = __float_as_int(v) >> 23;
            int enext = __shfl_down_sync(0xffffffffu, ebits, 1);
            ilog += ebits - 127;
            float rinv = __int_as_float((254 - ebits) << 23);
            int d = enext - ebits;
            d = (d > 60) ? 60 : ((d < -126) ? -126 : d);
            rho_b = fminf(rho_b * __int_as_float((d + 127) << 23), 1e30f);
            g0 *= rinv; g1 *= rinv; g2 *= rinv; g3 *= rinv; e *= rinv;
        };
        auto renorm_scan_b = [&]() {
            float v = fmaxf(fmaxf(g0, g1), fmaxf(fmaxf(g2, g3), e));
            #pragma unroll
            for (int d = 1; d < 32; d <<= 1) {
                float dn = __shfl_down_sync(0xffffffffu, v, d);
                v = (v > 0.0f) ? v : dn;
            }
            apply_scale_b(fmaxf(v, MFLOOR));
        };
        auto renorm_fast_b = [&]() {
            float v = fmaxf(fmaxf(g0, g1), fmaxf(fmaxf(g2, g3), e));
            apply_scale_b(fmaxf(v, MFLOOR));
        };

        for (int k = 0; k < RINGC - 1; k++) issue_k(k);

        for (int k = 0; k < HCHUNK; k++) {
            wait_k(k);
            __syncwarp();
            issue_k(k + RINGC - 1);
            const float* __restrict__ rows = slot_rows(k);
            const int tb = (63 - k) * CHUNK;
            const bool scan = (k < SCANCH);
            if (!virgin && (tb + CHUNK <= Tlen)) {
                #pragma unroll
                for (int i = CHUNK - 1; i >= 8; i--) stepbu(rows + i * C_DIM);
                if (scan) renorm_scan_b(); else renorm_fast_b();
                #pragma unroll
                for (int i = 7; i >= 0; i--) stepbu(rows + i * C_DIM);
                if (scan) renorm_scan_b(); else renorm_fast_b();
            } else {
                #pragma unroll
                for (int i = CHUNK - 1; i >= 8; i--) stepbg(tb + i, rows + i * C_DIM);
                if (scan) renorm_scan_b(); else renorm_fast_b();
                #pragma unroll
                for (int i = 7; i >= 0; i--) stepbg(tb + i, rows + i * C_DIM);
                if (scan) renorm_scan_b(); else renorm_fast_b();
            }
        }
        fg[s0] = g0; fg[s0 + 1] = g1; fg[s0 + 2] = g2; fg[s0 + 3] = g3;
        if (lane == 31) fg[128] = e;
        glc[lane] = (float)ilog * 0.6931471805599453f;
    }

    __syncthreads();

    // ===================== COMBINE (warp 0, log space) =====================
    if (wid == 0) {
        auto lcof = [&](const float* lc, int s) -> float {
            int l = s >> 2; if (l > 31) l = 31;
            return lc[l];
        };
        if (Tlen > HALF) {
            float vals[5];
            float M = NEGL;
            #pragma unroll
            for (int jj = 0; jj < 5; jj++) {
                int s = (jj < 4) ? (4 * lane + jj) : 128;
                bool own = (jj < 4) || (lane == 31);
                float v = NEGL;
                if (own && s < Smax) {
                    float la = __logf(fmaxf(fa[s], MFLOOR)) + lcof(flc, s);
                    float t0 = __logf(fmaxf(fg[s], MFLOOR)) + lcof(glc, s);
                    float t1 = NEGL, t2 = NEGL;
                    if (s + 1 < Smax)
                        t1 = __logf(fmaxf(fg[s + 1], MFLOOR)) + lcof(glc, s + 1);
                    if ((s & 1) && (s + 2 < Smax)) {
                        int li = (s - 1) >> 1;
                        if (li + 1 < LMAX && yb[li + 1] != yb[li])
                            t2 = __logf(fmaxf(fg[s + 2], MFLOOR)) + lcof(glc, s + 2);
                    }
                    float m3 = fmaxf(t0, fmaxf(t1, t2));
                    float lmix = m3 + __logf(__expf(t0 - m3) + __expf(t1 - m3) +
                                             __expf(t2 - m3));
                    v = la + lmix;
                }
                vals[jj] = v;
                M = fmaxf(M, v);
            }
            #pragma unroll
            for (int o = 16; o > 0; o >>= 1)
                M = fmaxf(M, __shfl_xor_sync(0xffffffffu, M, o));
            float ssum = 0.0f;
            #pragma unroll
            for (int jj = 0; jj < 5; jj++) ssum += __expf(vals[jj] - M);
            #pragma unroll
            for (int o = 16; o > 0; o >>= 1)
                ssum += __shfl_xor_sync(0xffffffffu, ssum, o);
            if (lane == 0) out[b] = -(M + __logf(ssum));
        } else if (lane == 0) {
            int  sa = 2 * L, sb = 2 * L - 1;
            float xa = __logf(fmaxf(fa[sa], MFLOOR)) + lcof(flc, sa);
            float xb = __logf(fmaxf(fa[sb], MFLOOR)) + lcof(flc, sb);
            float mxx = fmaxf(xa, xb), mnn = fminf(xa, xb);
            out[b] = -(mxx + __logf(1.0f + __expf(mnn - mxx)));
        }
    }
}

extern "C" void kernel_launch(void* const* d_in, const int* in_sizes, int n_in,
                              void* d_out, int out_size) {
    const int*   y_true  = (const int*)  d_in[0];   // [B,64] int32
    const float* y_pred  = (const float*)d_in[1];   // [B,1024,256] fp32
    const int*   in_len  = (const int*)  d_in[2];   // [B,1] int32
    const int*   lab_len = (const int*)  d_in[3];   // [B,1] int32
    float*       out     = (float*)      d_out;     // [B,1] fp32

    cudaFuncSetAttribute(ctc_loss_kernel,
                         cudaFuncAttributeMaxDynamicSharedMemorySize,
                         RING_BYTES);

    const int B = out_size;                          // 128
    ctc_loss_kernel<<<B, 64, RING_BYTES>>>(y_true, y_pred, in_len, lab_len, out);
}